// round 7
// baseline (speedup 1.0000x reference)
#include <cuda_runtime.h>
#include <cuda_bf16.h>

// FeedForwardQuantum: out = relu(cos(x+theta) @ W1 + b1) @ W2 + b2
// B=64, S=8192, E=8, F=32 -> 524288 rows.
// R4 changes vs R3 (18.9us, occ=22%, issue=38%):
//  - __launch_bounds__(256,3): cap regs at 85 -> 3 CTAs/SM (24 warps, 37.5% occ)
//  - GEMM2 streamed inside the GEMM1 column-pair loop: kills the 64-float
//    relu buffer, cutting live registers from ~124 to ~80 (no spills)
//  - weight LDS vectorized to 16B (ld.shared.v2.u64): 256 -> 128 weight
//    loads per 2 rows. w1 stored transposed-by-column-pair for contiguity.

#define E_DIM 8
#define F_DIM 32
#define N_ROWS (64 * 8192)
#define TPB 256
#define ROWS_PER_BLOCK (TPB * 2)
#define NBLOCKS (N_ROWS / ROWS_PER_BLOCK)   // 1024

typedef unsigned long long ull;

__device__ __forceinline__ ull pack2(float lo, float hi) {
    ull r;
    asm("mov.b64 %0, {%1, %2};" : "=l"(r) : "f"(lo), "f"(hi));
    return r;
}

__device__ __forceinline__ void unpack2(ull v, float &lo, float &hi) {
    asm("mov.b64 {%0, %1}, %2;" : "=f"(lo), "=f"(hi) : "l"(v));
}

__device__ __forceinline__ void ffma2(ull &d, ull a, ull b) {
    asm("fma.rn.f32x2 %0, %1, %2, %3;" : "=l"(d) : "l"(a), "l"(b), "l"(d));
}

__global__ __launch_bounds__(TPB, 3)
void ffq_kernel(const float* __restrict__ x,
                const float* __restrict__ theta,
                const float* __restrict__ w1,
                const float* __restrict__ b1,
                const float* __restrict__ w2,
                const float* __restrict__ b2,
                float* __restrict__ out) {
    // sw1t[jp][i] = (w1[i][2jp], w1[i][2jp+1])  -- transposed so the i-loop
    // reads contiguous 8B pairs -> 16B vector LDS.
    __shared__ __align__(16) ull sw1t[F_DIM / 2][E_DIM];  // [16][8]
    __shared__ __align__(16) ull sw2[F_DIM][E_DIM / 2];   // [32][4]
    __shared__ __align__(16) ull sb1[F_DIM / 2];
    __shared__ __align__(16) ull sb2[E_DIM / 2];
    __shared__ float sth[E_DIM];

    const int tid = threadIdx.x;

    if (tid < 128) {                          // 16*8 = 128 w1 pairs (transposed)
        int jp = tid >> 3, i = tid & 7;
        sw1t[jp][i] = pack2(w1[i * F_DIM + 2 * jp], w1[i * F_DIM + 2 * jp + 1]);
    } else {                                  // 32*4 = 128 w2 pairs
        int t = tid - 128;
        int k = t >> 2, j = t & 3;
        sw2[k][j] = pack2(w2[k * E_DIM + 2 * j], w2[k * E_DIM + 2 * j + 1]);
    }
    if (tid < 16)        sb1[tid]      = pack2(b1[2 * tid], b1[2 * tid + 1]);
    else if (tid < 20)   sb2[tid - 16] = pack2(b2[2 * (tid - 16)], b2[2 * (tid - 16) + 1]);
    else if (tid < 28)   sth[tid - 20] = theta[tid - 20];
    __syncthreads();

    const int r0 = blockIdx.x * ROWS_PER_BLOCK + tid;
    const int r1 = r0 + TPB;

    // ---- x rows, coalesced 16B loads ----
    const float4 a0 = *reinterpret_cast<const float4*>(x + (size_t)r0 * E_DIM);
    const float4 a1 = *reinterpret_cast<const float4*>(x + (size_t)r0 * E_DIM + 4);
    const float4 c0 = *reinterpret_cast<const float4*>(x + (size_t)r1 * E_DIM);
    const float4 c1 = *reinterpret_cast<const float4*>(x + (size_t)r1 * E_DIM + 4);

    float xv0[E_DIM] = {a0.x, a0.y, a0.z, a0.w, a1.x, a1.y, a1.z, a1.w};
    float xv1[E_DIM] = {c0.x, c0.y, c0.z, c0.w, c1.x, c1.y, c1.z, c1.w};

    // ---- q = cos(x+theta), pre-packed broadcast pairs (q,q) ----
    ull qd0[E_DIM], qd1[E_DIM];
    #pragma unroll
    for (int i = 0; i < E_DIM; i++) {
        float th = sth[i];
        float q0 = __cosf(xv0[i] + th);
        float q1 = __cosf(xv1[i] + th);
        qd0[i] = pack2(q0, q0);
        qd1[i] = pack2(q1, q1);
    }

    // ---- output accumulators (column pairs), init with b2 ----
    ull o0[E_DIM / 2], o1[E_DIM / 2];
    #pragma unroll
    for (int j = 0; j < E_DIM / 2; j++) {
        ull b = sb2[j];
        o0[j] = b;
        o1[j] = b;
    }

    // ---- fused GEMM1 column-pair -> relu -> GEMM2 accumulate ----
    #pragma unroll
    for (int jp = 0; jp < F_DIM / 2; jp++) {
        ull h0 = sb1[jp], h1 = sb1[jp];

        const ulonglong2* w1v = reinterpret_cast<const ulonglong2*>(&sw1t[jp][0]);
        #pragma unroll
        for (int ii = 0; ii < E_DIM / 2; ii++) {
            ulonglong2 w = w1v[ii];                 // 16B LDS: 2 weight pairs
            ffma2(h0, qd0[2 * ii],     w.x);
            ffma2(h1, qd1[2 * ii],     w.x);
            ffma2(h0, qd0[2 * ii + 1], w.y);
            ffma2(h1, qd1[2 * ii + 1], w.y);
        }

        // relu + broadcast-pack both h lanes (k = 2jp, 2jp+1), both rows
        float u, v;
        unpack2(h0, u, v);
        ull hb00 = pack2(fmaxf(u, 0.0f), fmaxf(u, 0.0f));
        ull hb01 = pack2(fmaxf(v, 0.0f), fmaxf(v, 0.0f));
        unpack2(h1, u, v);
        ull hb10 = pack2(fmaxf(u, 0.0f), fmaxf(u, 0.0f));
        ull hb11 = pack2(fmaxf(v, 0.0f), fmaxf(v, 0.0f));

        // GEMM2 rows k0 = 2jp, k1 = 2jp+1 (each 4 pairs = 2x 16B LDS)
        const ulonglong2* w2v0 = reinterpret_cast<const ulonglong2*>(&sw2[2 * jp][0]);
        const ulonglong2* w2v1 = reinterpret_cast<const ulonglong2*>(&sw2[2 * jp + 1][0]);
        #pragma unroll
        for (int jj = 0; jj < 2; jj++) {
            ulonglong2 wa = w2v0[jj];
            ffma2(o0[2 * jj],     hb00, wa.x);
            ffma2(o1[2 * jj],     hb10, wa.x);
            ffma2(o0[2 * jj + 1], hb00, wa.y);
            ffma2(o1[2 * jj + 1], hb10, wa.y);
            ulonglong2 wb = w2v1[jj];
            ffma2(o0[2 * jj],     hb01, wb.x);
            ffma2(o1[2 * jj],     hb11, wb.x);
            ffma2(o0[2 * jj + 1], hb01, wb.y);
            ffma2(o1[2 * jj + 1], hb11, wb.y);
        }
    }

    // ---- store ----
    float r0v[E_DIM], r1v[E_DIM];
    #pragma unroll
    for (int j = 0; j < E_DIM / 2; j++) {
        unpack2(o0[j], r0v[2 * j], r0v[2 * j + 1]);
        unpack2(o1[j], r1v[2 * j], r1v[2 * j + 1]);
    }
    *reinterpret_cast<float4*>(out + (size_t)r0 * E_DIM)     = make_float4(r0v[0], r0v[1], r0v[2], r0v[3]);
    *reinterpret_cast<float4*>(out + (size_t)r0 * E_DIM + 4) = make_float4(r0v[4], r0v[5], r0v[6], r0v[7]);
    *reinterpret_cast<float4*>(out + (size_t)r1 * E_DIM)     = make_float4(r1v[0], r1v[1], r1v[2], r1v[3]);
    *reinterpret_cast<float4*>(out + (size_t)r1 * E_DIM + 4) = make_float4(r1v[4], r1v[5], r1v[6], r1v[7]);
}

extern "C" void kernel_launch(void* const* d_in, const int* in_sizes, int n_in,
                              void* d_out, int out_size) {
    const float* x     = (const float*)d_in[0];   // [64, 8192, 8]
    const float* theta = (const float*)d_in[1];   // [8]
    const float* w1    = (const float*)d_in[2];   // [8, 32]
    const float* b1    = (const float*)d_in[3];   // [32]
    const float* w2    = (const float*)d_in[4];   // [32, 8]
    const float* b2    = (const float*)d_in[5];   // [8]
    float* out = (float*)d_out;                   // [64, 8192, 8]

    ffq_kernel<<<NBLOCKS, TPB>>>(x, theta, w1, b1, w2, b2, out);
}